// round 15
// baseline (speedup 1.0000x reference)
#include <cuda_runtime.h>
#include <cuda_bf16.h>
#include <cstdint>

// ---------------- problem constants ----------------
#define BB   16
#define NN   3136
#define DD   512
#define HDim 64
#define MM   (BB * NN)        // 50176 rows
#define HH   56
#define SPLIT 14
#define TOKS  (NN / SPLIT)    // 224 (= 7 chunks of 32 tokens)

// ---------------- scratch ----------------
__device__ __align__(256) float g_y[(size_t)MM * DD];
__device__ __align__(256) float g_v[(size_t)MM * DD];
__device__ __align__(256) float g_ctx_part[(size_t)SPLIT * 128 * 64 * 64];
__device__ __align__(256) float g_ksum_part[(size_t)SPLIT * 128 * 64];
__device__ __align__(256) float g_ksum[(size_t)128 * 64];
__device__ __align__(256) __nv_bfloat16 g_ctxhi[(size_t)128 * 4096];
__device__ __align__(256) __nv_bfloat16 g_ctxlo[(size_t)128 * 4096];

__device__ __align__(256) __nv_bfloat16 g_xhi[(size_t)MM * DD];
__device__ __align__(256) __nv_bfloat16 g_xlo[(size_t)MM * DD];
__device__ __align__(256) __nv_bfloat16 g_yhi[(size_t)MM * DD];
__device__ __align__(256) __nv_bfloat16 g_ylo[(size_t)MM * DD];
__device__ __align__(256) __nv_bfloat16 g_qhi[(size_t)MM * DD];
__device__ __align__(256) __nv_bfloat16 g_qlo[(size_t)MM * DD];
__device__ __align__(256) __nv_bfloat16 g_khi[(size_t)MM * DD];
__device__ __align__(256) __nv_bfloat16 g_klo[(size_t)MM * DD];
__device__ __align__(256) __nv_bfloat16 g_vhi[(size_t)MM * DD];
__device__ __align__(256) __nv_bfloat16 g_vlo[(size_t)MM * DD];
// transposed weights [n][k]: 0=Wq, 1=Wkv(k), 2=Wkv(v), 3=Wp
__device__ __align__(256) __nv_bfloat16 g_whi[4][(size_t)DD * DD];
__device__ __align__(256) __nv_bfloat16 g_wlo[4][(size_t)DD * DD];

// ---------------- helpers ----------------
__device__ __forceinline__ uint32_t smem_to_u32(const void* p) {
    uint32_t a;
    asm("{ .reg .u64 t; cvta.to.shared.u64 t, %1; cvt.u32.u64 %0, t; }" : "=r"(a) : "l"(p));
    return a;
}
#define SWZ(o) ((o) ^ (((o) >> 3) & 0x70))

#define CP16(dst, src) \
    asm volatile("cp.async.cg.shared.global [%0], [%1], 16;" :: "r"(dst), "l"(src) : "memory")
#define CP_COMMIT() asm volatile("cp.async.commit_group;" ::: "memory")
#define CP_WAIT0()  asm volatile("cp.async.wait_group 0;" ::: "memory")
#define CP_WAIT1()  asm volatile("cp.async.wait_group 1;" ::: "memory")

__device__ __forceinline__ void ldsm4(uint32_t addr, uint32_t* r) {
    asm volatile("ldmatrix.sync.aligned.m8n8.x4.shared.b16 {%0,%1,%2,%3}, [%4];"
                 : "=r"(r[0]), "=r"(r[1]), "=r"(r[2]), "=r"(r[3]) : "r"(addr));
}
__device__ __forceinline__ void ldsm4t(uint32_t addr, uint32_t* r) {
    asm volatile("ldmatrix.sync.aligned.m8n8.x4.trans.shared.b16 {%0,%1,%2,%3}, [%4];"
                 : "=r"(r[0]), "=r"(r[1]), "=r"(r[2]), "=r"(r[3]) : "r"(addr));
}
__device__ __forceinline__ void mma16816(float* d, const uint32_t* a, const uint32_t* b) {
    asm volatile(
        "mma.sync.aligned.m16n8k16.row.col.f32.bf16.bf16.f32 "
        "{%0,%1,%2,%3}, {%4,%5,%6,%7}, {%8,%9}, {%0,%1,%2,%3};"
        : "+f"(d[0]), "+f"(d[1]), "+f"(d[2]), "+f"(d[3])
        : "r"(a[0]), "r"(a[1]), "r"(a[2]), "r"(a[3]), "r"(b[0]), "r"(b[1]));
}
__device__ __forceinline__ void split_store(__nv_bfloat16* hi, __nv_bfloat16* lo,
                                            size_t idx, float v0, float v1) {
    __nv_bfloat16 h0 = __float2bfloat16(v0), h1 = __float2bfloat16(v1);
    __nv_bfloat16 l0 = __float2bfloat16(v0 - __bfloat162float(h0));
    __nv_bfloat16 l1 = __float2bfloat16(v1 - __bfloat162float(h1));
    *(__nv_bfloat162*)(hi + idx) = __nv_bfloat162(h0, h1);
    *(__nv_bfloat162*)(lo + idx) = __nv_bfloat162(l0, l1);
}

// ---------------- input split kernels ----------------
__global__ __launch_bounds__(256)
void split_x_kernel(const float* __restrict__ x)
{
    size_t i = (size_t)blockIdx.x * 256 + threadIdx.x;   // over MM*DD/4
    float4 v = ((const float4*)x)[i];
    split_store(g_xhi, g_xlo, 4 * i + 0, v.x, v.y);
    split_store(g_xhi, g_xlo, 4 * i + 2, v.z, v.w);
}

__global__ __launch_bounds__(256)
void prep_w_kernel(const float* __restrict__ Wq, const float* __restrict__ Wkv,
                   const float* __restrict__ Wp)
{
    int idx = blockIdx.x * 256 + threadIdx.x;   // output [n][k]
    int n = idx / DD, k = idx % DD;
    float v0 = Wq[(size_t)k * DD + n];
    float v1 = Wkv[(size_t)k * 2 * DD + n];
    float v2 = Wkv[(size_t)k * 2 * DD + DD + n];
    float v3 = Wp[(size_t)k * DD + n];
#pragma unroll
    for (int m = 0; m < 4; m++) {
        float v = (m == 0) ? v0 : (m == 1) ? v1 : (m == 2) ? v2 : v3;
        __nv_bfloat16 h = __float2bfloat16(v);
        g_whi[m][idx] = h;
        g_wlo[m][idx] = __float2bfloat16(v - __bfloat162float(h));
    }
}

// ---------------- HMMA GEMM core: 512 threads, 16 warps (4m x 4n), 2-stage,
// ----------------- register-level fragment double-buffering across kk ----------------
#define ST_AHI 0
#define ST_ALO 16384
#define ST_BHI 32768
#define ST_BLO 49152
#define STAGE_BYTES 65536
#define GEMM_SMEM (2 * STAGE_BYTES)   // 131072
#define GT 512

__device__ __forceinline__ void gemm_load_chunk(
    char* smem, int stage, int c, int m0, int n0, int tid,
    const __nv_bfloat16* __restrict__ Ahi, const __nv_bfloat16* __restrict__ Alo,
    const __nv_bfloat16* __restrict__ Bhi, const __nv_bfloat16* __restrict__ Blo)
{
    const uint32_t sb = smem_to_u32(smem) + stage * STAGE_BYTES;
#pragma unroll
    for (int i = 0; i < 2; i++) {
        int u = tid + i * GT;           // 0..1023 16B units
        int row = u >> 3, col = u & 7;
        uint32_t off = SWZ((uint32_t)(row * 128 + col * 16));
        size_t ga = (size_t)(m0 + row) * DD + c * 64 + col * 8;
        size_t gb = (size_t)(n0 + row) * DD + c * 64 + col * 8;
        CP16(sb + ST_AHI + off, Ahi + ga);
        CP16(sb + ST_ALO + off, Alo + ga);
        CP16(sb + ST_BHI + off, Bhi + gb);
        CP16(sb + ST_BLO + off, Blo + gb);
    }
    CP_COMMIT();
}

// load all 8 fragment quadruples for one kk group
__device__ __forceinline__ void gemm_ld_frags(
    uint32_t st, int kk, int wm, int wn, int lane,
    uint32_t ah[2][4], uint32_t al[2][4], uint32_t bh[2][4], uint32_t bl[2][4])
{
#pragma unroll
    for (int mi = 0; mi < 2; mi++) {
        int row = wm * 32 + mi * 16 + (lane & 15);
        uint32_t off = SWZ((uint32_t)(row * 128 + kk * 32 + (lane >> 4) * 16));
        ldsm4(st + ST_AHI + off, ah[mi]);
        ldsm4(st + ST_ALO + off, al[mi]);
    }
#pragma unroll
    for (int g = 0; g < 2; g++) {
        int n = wn * 32 + g * 16 + (lane & 7) + ((lane & 16) ? 8 : 0);
        uint32_t off = SWZ((uint32_t)(n * 128 + kk * 32 + ((lane >> 3) & 1) * 16));
        ldsm4(st + ST_BHI + off, bh[g]);
        ldsm4(st + ST_BLO + off, bl[g]);
    }
}

__device__ __forceinline__ void gemm_mma_group(
    float acc[2][4][4],
    uint32_t ah[2][4], uint32_t al[2][4], uint32_t bh[2][4], uint32_t bl[2][4])
{
#pragma unroll
    for (int mi = 0; mi < 2; mi++)
#pragma unroll
        for (int nt = 0; nt < 4; nt++) {
            const uint32_t* h2 = &bh[nt >> 1][(nt & 1) * 2];
            const uint32_t* l2 = &bl[nt >> 1][(nt & 1) * 2];
            mma16816(acc[mi][nt], ah[mi], h2);
            mma16816(acc[mi][nt], ah[mi], l2);
            mma16816(acc[mi][nt], al[mi], h2);
        }
}

__device__ __forceinline__ void gemm_mainloop(
    char* smem, int m0, int n0, int tid, int wm, int wn, int lane,
    const __nv_bfloat16* Ahi, const __nv_bfloat16* Alo,
    const __nv_bfloat16* Bhi, const __nv_bfloat16* Blo,
    float acc[2][4][4])
{
    gemm_load_chunk(smem, 0, 0, m0, n0, tid, Ahi, Alo, Bhi, Blo);
    const uint32_t sbase = smem_to_u32(smem);

    uint32_t ah[2][2][4], al[2][2][4], bh[2][2][4], bl[2][2][4];

    for (int c = 0; c < 8; c++) {
        CP_WAIT0();
        __syncthreads();
        if (c < 7)
            gemm_load_chunk(smem, (c + 1) & 1, c + 1, m0, n0, tid, Ahi, Alo, Bhi, Blo);
        const uint32_t st = sbase + (c & 1) * STAGE_BYTES;

        gemm_ld_frags(st, 0, wm, wn, lane, ah[0], al[0], bh[0], bl[0]);
#pragma unroll
        for (int kk = 0; kk < 4; kk++) {
            if (kk < 3)
                gemm_ld_frags(st, kk + 1, wm, wn, lane,
                              ah[(kk + 1) & 1], al[(kk + 1) & 1],
                              bh[(kk + 1) & 1], bl[(kk + 1) & 1]);
            gemm_mma_group(acc, ah[kk & 1], al[kk & 1], bh[kk & 1], bl[kk & 1]);
        }
    }
}

// ---------------- fused QKV GEMM: epilogue emits bf16 hi/lo (+ f32 v for dwc) ----------------
__global__ __launch_bounds__(GT, 1)
void gemm_qkv(const __nv_bfloat16* __restrict__ Ahi, const __nv_bfloat16* __restrict__ Alo,
              const __nv_bfloat16* __restrict__ Bhi, const __nv_bfloat16* __restrict__ Blo,
              const float* __restrict__ pos)
{
    extern __shared__ char smem[];
    const int tid = threadIdx.x;
    const int wid = tid >> 5, lane = tid & 31;
    const int wm = wid & 3, wn = wid >> 2;
    const int m0 = blockIdx.y * 128;
    const int n0 = blockIdx.x * 128;
    const int mode = blockIdx.x >> 2;          // 0=q 1=k 2=v
    const int ncol0 = n0 - mode * 512;

    float acc[2][4][4] = {};
    gemm_mainloop(smem, m0, n0, tid, wm, wn, lane, Ahi, Alo, Bhi, Blo, acc);

    __nv_bfloat16 *Ohi, *Olo;
    if (mode == 0)      { Ohi = g_qhi; Olo = g_qlo; }
    else if (mode == 1) { Ohi = g_khi; Olo = g_klo; }
    else                { Ohi = g_vhi; Olo = g_vlo; }

#pragma unroll
    for (int mi = 0; mi < 2; mi++) {
#pragma unroll
        for (int nt = 0; nt < 4; nt++) {
            int r0 = m0 + wm * 32 + mi * 16 + (lane >> 2);
            int col = ncol0 + wn * 32 + nt * 8 + (lane & 3) * 2;
#pragma unroll
            for (int half = 0; half < 2; half++) {
                int r = r0 + half * 8;
                float v0 = acc[mi][nt][half * 2 + 0];
                float v1 = acc[mi][nt][half * 2 + 1];
                if (mode == 1) {
                    const float2 pe = *(const float2*)(pos + (size_t)(r % NN) * DD + col);
                    v0 += pe.x; v1 += pe.y;
                }
                if (mode != 2) { v0 = fmaxf(v0, 0.f); v1 = fmaxf(v1, 0.f); }
                split_store(Ohi, Olo, (size_t)r * DD + col, v0, v1);
                if (mode == 2)
                    *(float2*)(g_v + (size_t)r * DD + col) = make_float2(v0, v1);
            }
        }
    }
}

// ---------------- final GEMM: out = y @ Wp + bp ----------------
__global__ __launch_bounds__(GT, 1)
void gemm_out(const __nv_bfloat16* __restrict__ Ahi, const __nv_bfloat16* __restrict__ Alo,
              const __nv_bfloat16* __restrict__ Bhi, const __nv_bfloat16* __restrict__ Blo,
              float* __restrict__ C, const float* __restrict__ bias)
{
    extern __shared__ char smem[];
    const int tid = threadIdx.x;
    const int wid = tid >> 5, lane = tid & 31;
    const int wm = wid & 3, wn = wid >> 2;
    const int m0 = blockIdx.y * 128;
    const int n0 = blockIdx.x * 128;

    float acc[2][4][4] = {};
    gemm_mainloop(smem, m0, n0, tid, wm, wn, lane, Ahi, Alo, Bhi, Blo, acc);

#pragma unroll
    for (int mi = 0; mi < 2; mi++) {
#pragma unroll
        for (int nt = 0; nt < 4; nt++) {
            int r0 = m0 + wm * 32 + mi * 16 + (lane >> 2);
            int col = n0 + wn * 32 + nt * 8 + (lane & 3) * 2;
            const float2 bb = *(const float2*)(bias + col);
#pragma unroll
            for (int half = 0; half < 2; half++) {
                int r = r0 + half * 8;
                *(float2*)(C + (size_t)r * DD + col) =
                    make_float2(acc[mi][nt][half * 2 + 0] + bb.x,
                                acc[mi][nt][half * 2 + 1] + bb.y);
            }
        }
    }
}

// ---------------- ctx via HMMA + ldsm.trans, pre-split bf16 inputs (validated) ----------------
#define CTX_SMEM (3 * 16384)   // 49152

__global__ __launch_bounds__(128)
void ctx_mma_kernel()
{
    extern __shared__ char cs[];
    const int bh = blockIdx.x;          // 0..127
    const int s  = blockIdx.y;          // 0..SPLIT-1
    const int b = bh >> 3, h = bh & 7;
    const int tid = threadIdx.x, lane = tid & 31, wid = tid >> 5;
    const int wm = wid & 1, wn = wid >> 1;
    const uint32_t sb = smem_to_u32(cs);

    const size_t rowbase = ((size_t)(b * NN) + (size_t)s * TOKS) * DD + h * HDim;
    const __nv_bfloat16* src0 = g_khi + rowbase;
    const __nv_bfloat16* src1 = g_klo + rowbase;
    const __nv_bfloat16* src2 = g_vhi + rowbase;
    const __nv_bfloat16* src3 = g_vlo + rowbase;

    float acc[2][4][4] = {};
    float ks[2][2] = {};

#define CTX_LOAD(c, st) do {                                                    \
    uint32_t base_ = sb + (st) * 16384;                                         \
    _Pragma("unroll")                                                           \
    for (int i_ = 0; i_ < 8; i_++) {                                            \
        int u_ = tid + i_ * 128;                                                \
        int arr_ = u_ >> 8, rem_ = u_ & 255, row_ = rem_ >> 3, col_ = rem_ & 7; \
        uint32_t dst_ = base_ + arr_ * 4096 + SWZ((uint32_t)(row_ * 128 + col_ * 16)); \
        const __nv_bfloat16* sp_ = (arr_ == 0) ? src0 : (arr_ == 1) ? src1      \
                                  : (arr_ == 2) ? src2 : src3;                  \
        CP16(dst_, sp_ + (size_t)((c) * 32 + row_) * DD + col_ * 8);            \
    }                                                                           \
    CP_COMMIT();                                                                \
} while (0)

    CTX_LOAD(0, 0);
    CTX_LOAD(1, 1);

    for (int c = 0; c < 7; c++) {
        if (c < 6) { CP_WAIT1(); } else { CP_WAIT0(); }
        __syncthreads();
        if (c < 5) CTX_LOAD(c + 2, (c + 2) % 3);
        const uint32_t st = sb + (c % 3) * 16384;
#pragma unroll
        for (int kk = 0; kk < 2; kk++) {
            uint32_t ah[2][4], al[2][4], bh2[2][4], bl2[2][4];
#pragma unroll
            for (int mi = 0; mi < 2; mi++) {
                int wd = wm * 32 + mi * 16;
                int tokrow = kk * 16 + (lane & 7) + ((lane & 16) ? 8 : 0);
                uint32_t off = SWZ((uint32_t)(tokrow * 128 + wd * 2 + ((lane >> 3) & 1) * 16));
                ldsm4t(st + 0 + off, ah[mi]);
                ldsm4t(st + 4096 + off, al[mi]);
            }
#pragma unroll
            for (int g = 0; g < 2; g++) {
                int eb = wn * 32 + g * 16;
                int tokrow = kk * 16 + (lane & 7) + ((lane & 8) ? 8 : 0);
                uint32_t off = SWZ((uint32_t)(tokrow * 128 + eb * 2 + ((lane >> 4) & 1) * 16));
                ldsm4t(st + 8192 + off, bh2[g]);
                ldsm4t(st + 12288 + off, bl2[g]);
            }
#pragma unroll
            for (int mi = 0; mi < 2; mi++)
#pragma unroll
                for (int nt = 0; nt < 4; nt++) {
                    const uint32_t* h2 = &bh2[nt >> 1][(nt & 1) * 2];
                    const uint32_t* l2 = &bl2[nt >> 1][(nt & 1) * 2];
                    mma16816(acc[mi][nt], ah[mi], h2);
                    mma16816(acc[mi][nt], ah[mi], l2);
                    mma16816(acc[mi][nt], al[mi], h2);
                }
            if (wn == 0) {
#pragma unroll
                for (int mi = 0; mi < 2; mi++)
#pragma unroll
                    for (int rr = 0; rr < 2; rr++) {
                        float2 x0 = __bfloat1622float2(*(__nv_bfloat162*)&ah[mi][rr]);
                        float2 x2 = __bfloat1622float2(*(__nv_bfloat162*)&ah[mi][rr + 2]);
                        float2 y0 = __bfloat1622float2(*(__nv_bfloat162*)&al[mi][rr]);
                        float2 y2 = __bfloat1622float2(*(__nv_bfloat162*)&al[mi][rr + 2]);
                        ks[mi][rr] += x0.x + x0.y + x2.x + x2.y + y0.x + y0.y + y2.x + y2.y;
                    }
            }
        }
    }

    float* cp = g_ctx_part + ((size_t)s * 128 + bh) * 4096;
#pragma unroll
    for (int mi = 0; mi < 2; mi++)
#pragma unroll
        for (int nt = 0; nt < 4; nt++) {
            int r = wm * 32 + mi * 16 + (lane >> 2);
            int col = wn * 32 + nt * 8 + (lane & 3) * 2;
            *(float2*)&cp[r * 64 + col] = make_float2(acc[mi][nt][0], acc[mi][nt][1]);
            *(float2*)&cp[(r + 8) * 64 + col] = make_float2(acc[mi][nt][2], acc[mi][nt][3]);
        }

#pragma unroll
    for (int mi = 0; mi < 2; mi++)
#pragma unroll
        for (int rr = 0; rr < 2; rr++) {
            ks[mi][rr] += __shfl_xor_sync(0xffffffffu, ks[mi][rr], 1);
            ks[mi][rr] += __shfl_xor_sync(0xffffffffu, ks[mi][rr], 2);
        }
    if (wn == 0 && (lane & 3) == 0) {
        float* kp = g_ksum_part + ((size_t)s * 128 + bh) * 64;
#pragma unroll
        for (int mi = 0; mi < 2; mi++)
#pragma unroll
            for (int rr = 0; rr < 2; rr++)
                kp[wm * 32 + mi * 16 + (lane >> 2) + rr * 8] = ks[mi][rr];
    }
}

// ---------------- reduce: sum partials, emit ctx bf16 hi/lo + ksum f32 ----------------
__global__ void reduce_kernel()
{
    const int idx = blockIdx.x * 256 + threadIdx.x;
    if (idx < 128 * 4096) {
        float s = 0.f;
#pragma unroll
        for (int p = 0; p < SPLIT; p++) s += g_ctx_part[(size_t)p * 128 * 4096 + idx];
        __nv_bfloat16 hi = __float2bfloat16(s);
        g_ctxhi[idx] = hi;
        g_ctxlo[idx] = __float2bfloat16(s - __bfloat162float(hi));
    } else {
        const int i2 = idx - 128 * 4096;
        if (i2 < 128 * 64) {
            float s = 0.f;
#pragma unroll
            for (int p = 0; p < SPLIT; p++) s += g_ksum_part[(size_t)p * 128 * 64 + i2];
            g_ksum[i2] = s;
        }
    }
}

// ---------------- attn via HMMA: y = (q @ ctx) * dinv ----------------
__global__ __launch_bounds__(128)
void attn_mma_kernel()
{
    __shared__ __align__(16) char abuf[4][8192];   // qhi, qlo, ctxhi, ctxlo
    __shared__ float ksumS[64];
    __shared__ float dinv[64];

    const int n0 = blockIdx.x * 64;
    const int bh = blockIdx.y;
    const int b = bh >> 3, h = bh & 7;
    const int tid = threadIdx.x, lane = tid & 31, wn = tid >> 5;
    const uint32_t sb = smem_to_u32(abuf);

    const size_t qbase = ((size_t)(b * NN) + n0) * DD + h * HDim;
#pragma unroll
    for (int i = 0; i < 16; i++) {
        int u = tid + i * 128;
        int arr = u >> 9, rem = u & 511, row = rem >> 3, col = rem & 7;
        uint32_t dst = sb + arr * 8192 + SWZ((uint32_t)(row * 128 + col * 16));
        const __nv_bfloat16* src;
        if (arr == 0)      src = g_qhi + qbase + (size_t)row * DD + col * 8;
        else if (arr == 1) src = g_qlo + qbase + (size_t)row * DD + col * 8;
        else if (arr == 2) src = g_ctxhi + (size_t)bh * 4096 + row * 64 + col * 8;
        else               src = g_ctxlo + (size_t)bh * 4096 + row * 64 + col * 8;
        CP16(dst, src);
    }
    CP_COMMIT();
    if (tid >= 64) ksumS[tid - 64] = g_ksum[bh * 64 + tid - 64];
    CP_WAIT0();
    __syncthreads();

    if (tid < 64) {
        float ssum = 0.f;
#pragma unroll
        for (int c8 = 0; c8 < 8; c8++) {
            uint32_t off = SWZ((uint32_t)(tid * 128 + c8 * 16));
#pragma unroll
            for (int j = 0; j < 8; j++) {
                float qv = __bfloat162float(*(__nv_bfloat16*)(abuf[0] + off + j * 2))
                         + __bfloat162float(*(__nv_bfloat16*)(abuf[1] + off + j * 2));
                ssum = fmaf(qv, ksumS[c8 * 8 + j], ssum);
            }
        }
        dinv[tid] = 1.0f / (ssum + 1e-6f);
    }
    __syncthreads();

    float acc[4][2][4] = {};
    const uint32_t q_hi = sb, q_lo = sb + 8192, c_hi = sb + 16384, c_lo = sb + 24576;
#pragma unroll
    for (int kk = 0; kk < 4; kk++) {
        uint32_t ah[4][4], al[4][4], bh2[4], bl2[4];
#pragma unroll
        for (int mi = 0; mi < 4; mi++) {
            int row = mi * 16 + (lane & 15);
            uint32_t off = SWZ((uint32_t)(row * 128 + kk * 32 + (lane >> 4) * 16));
            ldsm4(q_hi + off, ah[mi]);
            ldsm4(q_lo + off, al[mi]);
        }
        {
            int drow = kk * 16 + (lane & 7) + ((lane & 8) ? 8 : 0);
            uint32_t off = SWZ((uint32_t)(drow * 128 + wn * 32 + ((lane >> 4) & 1) * 16));
            ldsm4t(c_hi + off, bh2);
            ldsm4t(c_lo + off, bl2);
        }
#pragma unroll
        for (int mi = 0; mi < 4; mi++)
#pragma unroll
            for (int nt = 0; nt < 2; nt++) {
                mma16816(acc[mi][nt], ah[mi], &bh2[nt * 2]);
                mma16816(acc[mi][nt], ah[mi], &bl2[nt * 2]);
                mma16816(acc[mi][nt], al[mi], &bh2[nt * 2]);
            }
    }

    float* yb = g_y + ((size_t)bh * NN + n0) * HDim;
#pragma unroll
    for (int mi = 0; mi < 4; mi++)
#pragma unroll
        for (int nt = 0; nt < 2; nt++) {
            int r = mi * 16 + (lane >> 2);
            int col = wn * 16 + nt * 8 + (lane & 3) * 2;
            float d0 = dinv[r], d1 = dinv[r + 8];
            *(float2*)&yb[(size_t)r * 64 + col] =
                make_float2(acc[mi][nt][0] * d0, acc[mi][nt][1] * d0);
            *(float2*)&yb[(size_t)(r + 8) * 64 + col] =
                make_float2(acc[mi][nt][2] * d1, acc[mi][nt][3] * d1);
        }
}

// ---------------- dwc: depthwise 5x5 over f32 v + fused bf16 split of y ----------------
__global__ __launch_bounds__(256)
void dwc_kernel(const float* __restrict__ w, const float* __restrict__ bias)
{
    const int bh = blockIdx.y;
    const int b = bh >> 3, h = bh & 7;
    const int tid = threadIdx.x;

    __shared__ float ws[64 * 25];
    __shared__ float bs[64];
    for (int i = tid; i < 64 * 25; i += 256) ws[i] = w[i];
    if (tid < 64) bs[tid] = bias[tid];
    __syncthreads();

    const int c = tid & 63;
    const int p = blockIdx.x * 4 + (tid >> 6);
    const int pi = p / HH, pj = p % HH;

    const float* vbase = g_v + (size_t)(b * NN) * DD + h * HDim + c;
    float acc = 0.f;
#pragma unroll
    for (int di = 0; di < 5; di++) {
        const int ii = pi + di - 2;
        if ((unsigned)ii < (unsigned)HH) {
#pragma unroll
            for (int dj = 0; dj < 5; dj++) {
                const int jj = pj + dj - 2;
                if ((unsigned)jj < (unsigned)HH)
                    acc = fmaf(ws[c * 25 + di * 5 + dj],
                               vbase[(size_t)(ii * HH + jj) * DD], acc);
            }
        }
    }
    const size_t yi = ((size_t)bh * NN + p) * HDim + c;
    float total = g_y[yi] + acc + bs[c];
    __nv_bfloat16 hi = __float2bfloat16(total);
    g_yhi[yi] = hi;
    g_ylo[yi] = __float2bfloat16(total - __bfloat162float(hi));
}

// ---------------- launch ----------------
extern "C" void kernel_launch(void* const* d_in, const int* in_sizes, int n_in,
                              void* d_out, int out_size)
{
    const float* x    = (const float*)d_in[0];
    const float* Wq   = (const float*)d_in[1];
    const float* Wkv  = (const float*)d_in[2];
    const float* pos  = (const float*)d_in[3];
    const float* dwcw = (const float*)d_in[4];
    const float* dwcb = (const float*)d_in[5];
    const float* Wp   = (const float*)d_in[6];
    const float* bp   = (const float*)d_in[7];
    float* out = (float*)d_out;

    __nv_bfloat16 *xhip, *xlop, *yhip, *ylop, *whip, *wlop;
    cudaGetSymbolAddress((void**)&xhip, g_xhi);
    cudaGetSymbolAddress((void**)&xlop, g_xlo);
    cudaGetSymbolAddress((void**)&yhip, g_yhi);
    cudaGetSymbolAddress((void**)&ylop, g_ylo);
    cudaGetSymbolAddress((void**)&whip, g_whi);
    cudaGetSymbolAddress((void**)&wlop, g_wlo);

    cudaFuncSetAttribute(gemm_qkv, cudaFuncAttributeMaxDynamicSharedMemorySize, GEMM_SMEM);
    cudaFuncSetAttribute(gemm_out, cudaFuncAttributeMaxDynamicSharedMemorySize, GEMM_SMEM);
    cudaFuncSetAttribute(ctx_mma_kernel, cudaFuncAttributeMaxDynamicSharedMemorySize, CTX_SMEM);

    split_x_kernel<<<(MM * DD / 4) / 256, 256>>>(x);
    prep_w_kernel<<<(DD * DD) / 256, 256>>>(Wq, Wkv, Wp);

    const size_t WSZ = (size_t)DD * DD;
    gemm_qkv<<<dim3(12, MM / 128), GT, GEMM_SMEM>>>(xhip, xlop, whip, wlop, pos);

    ctx_mma_kernel<<<dim3(128, SPLIT), 128, CTX_SMEM>>>();
    reduce_kernel<<<(128 * 4096 + 128 * 64) / 256, 256>>>();
    attn_mma_kernel<<<dim3(NN / 64, 128), 128>>>();
    dwc_kernel<<<dim3(NN / 4, 128), 256>>>(dwcw, dwcb);

    gemm_out<<<dim3(4, MM / 128), GT, GEMM_SMEM>>>(
        yhip, ylop, whip + 3 * WSZ, wlop + 3 * WSZ, out, bp);
}

// round 17
// speedup vs baseline: 1.1064x; 1.1064x over previous
#include <cuda_runtime.h>
#include <cuda_bf16.h>
#include <cstdint>

// ---------------- problem constants ----------------
#define BB   16
#define NN   3136
#define DD   512
#define HDim 64
#define MM   (BB * NN)        // 50176 rows
#define HH   56
#define SPLIT 14
#define TOKS  (NN / SPLIT)    // 224 (= 7 chunks of 32 tokens)

// ---------------- scratch ----------------
__device__ __align__(256) float g_y[(size_t)MM * DD];
__device__ __align__(256) float g_v[(size_t)MM * DD];
__device__ __align__(256) float g_ctx_part[(size_t)SPLIT * 128 * 64 * 64];
__device__ __align__(256) float g_ksum_part[(size_t)SPLIT * 128 * 64];
__device__ __align__(256) float g_ksum[(size_t)128 * 64];
__device__ __align__(256) __nv_bfloat16 g_ctxhi[(size_t)128 * 4096];
__device__ __align__(256) __nv_bfloat16 g_ctxlo[(size_t)128 * 4096];

__device__ __align__(256) __nv_bfloat16 g_xhi[(size_t)MM * DD];
__device__ __align__(256) __nv_bfloat16 g_xlo[(size_t)MM * DD];
__device__ __align__(256) __nv_bfloat16 g_yhi[(size_t)MM * DD];
__device__ __align__(256) __nv_bfloat16 g_ylo[(size_t)MM * DD];
__device__ __align__(256) __nv_bfloat16 g_qhi[(size_t)MM * DD];
__device__ __align__(256) __nv_bfloat16 g_qlo[(size_t)MM * DD];
__device__ __align__(256) __nv_bfloat16 g_khi[(size_t)MM * DD];
__device__ __align__(256) __nv_bfloat16 g_klo[(size_t)MM * DD];
__device__ __align__(256) __nv_bfloat16 g_vhi[(size_t)MM * DD];
__device__ __align__(256) __nv_bfloat16 g_vlo[(size_t)MM * DD];
// transposed weights [n][k]: 0=Wq, 1=Wkv(k), 2=Wkv(v), 3=Wp
__device__ __align__(256) __nv_bfloat16 g_whi[4][(size_t)DD * DD];
__device__ __align__(256) __nv_bfloat16 g_wlo[4][(size_t)DD * DD];

// ---------------- helpers ----------------
__device__ __forceinline__ uint32_t smem_to_u32(const void* p) {
    uint32_t a;
    asm("{ .reg .u64 t; cvta.to.shared.u64 t, %1; cvt.u32.u64 %0, t; }" : "=r"(a) : "l"(p));
    return a;
}
#define SWZ(o) ((o) ^ (((o) >> 3) & 0x70))

#define CP16(dst, src) \
    asm volatile("cp.async.cg.shared.global [%0], [%1], 16;" :: "r"(dst), "l"(src) : "memory")
#define CP_COMMIT() asm volatile("cp.async.commit_group;" ::: "memory")
#define CP_WAIT0()  asm volatile("cp.async.wait_group 0;" ::: "memory")
#define CP_WAIT1()  asm volatile("cp.async.wait_group 1;" ::: "memory")

__device__ __forceinline__ void ldsm4(uint32_t addr, uint32_t* r) {
    asm volatile("ldmatrix.sync.aligned.m8n8.x4.shared.b16 {%0,%1,%2,%3}, [%4];"
                 : "=r"(r[0]), "=r"(r[1]), "=r"(r[2]), "=r"(r[3]) : "r"(addr));
}
__device__ __forceinline__ void ldsm4t(uint32_t addr, uint32_t* r) {
    asm volatile("ldmatrix.sync.aligned.m8n8.x4.trans.shared.b16 {%0,%1,%2,%3}, [%4];"
                 : "=r"(r[0]), "=r"(r[1]), "=r"(r[2]), "=r"(r[3]) : "r"(addr));
}
__device__ __forceinline__ void mma16816(float* d, const uint32_t* a, const uint32_t* b) {
    asm volatile(
        "mma.sync.aligned.m16n8k16.row.col.f32.bf16.bf16.f32 "
        "{%0,%1,%2,%3}, {%4,%5,%6,%7}, {%8,%9}, {%0,%1,%2,%3};"
        : "+f"(d[0]), "+f"(d[1]), "+f"(d[2]), "+f"(d[3])
        : "r"(a[0]), "r"(a[1]), "r"(a[2]), "r"(a[3]), "r"(b[0]), "r"(b[1]));
}
__device__ __forceinline__ void split_store(__nv_bfloat16* hi, __nv_bfloat16* lo,
                                            size_t idx, float v0, float v1) {
    __nv_bfloat16 h0 = __float2bfloat16(v0), h1 = __float2bfloat16(v1);
    __nv_bfloat16 l0 = __float2bfloat16(v0 - __bfloat162float(h0));
    __nv_bfloat16 l1 = __float2bfloat16(v1 - __bfloat162float(h1));
    *(__nv_bfloat162*)(hi + idx) = __nv_bfloat162(h0, h1);
    *(__nv_bfloat162*)(lo + idx) = __nv_bfloat162(l0, l1);
}

// ---------------- input split kernels ----------------
__global__ __launch_bounds__(256)
void split_x_kernel(const float* __restrict__ x)
{
    size_t i = (size_t)blockIdx.x * 256 + threadIdx.x;   // over MM*DD/4
    float4 v = ((const float4*)x)[i];
    split_store(g_xhi, g_xlo, 4 * i + 0, v.x, v.y);
    split_store(g_xhi, g_xlo, 4 * i + 2, v.z, v.w);
}

__global__ __launch_bounds__(256)
void prep_w_kernel(const float* __restrict__ Wq, const float* __restrict__ Wkv,
                   const float* __restrict__ Wp)
{
    int idx = blockIdx.x * 256 + threadIdx.x;   // output [n][k]
    int n = idx / DD, k = idx % DD;
    float v0 = Wq[(size_t)k * DD + n];
    float v1 = Wkv[(size_t)k * 2 * DD + n];
    float v2 = Wkv[(size_t)k * 2 * DD + DD + n];
    float v3 = Wp[(size_t)k * DD + n];
#pragma unroll
    for (int m = 0; m < 4; m++) {
        float v = (m == 0) ? v0 : (m == 1) ? v1 : (m == 2) ? v2 : v3;
        __nv_bfloat16 h = __float2bfloat16(v);
        g_whi[m][idx] = h;
        g_wlo[m][idx] = __float2bfloat16(v - __bfloat162float(h));
    }
}

// ---------------- HMMA GEMM core: 256 threads, 8 warps (2m x 4n), tile 128x64,
// ---------------- 2 CTAs/SM (independent barrier domains hide sync stalls) ----------------
#define SA_HI 0
#define SA_LO 16384
#define SB_HI 32768
#define SB_LO 40960
#define STAGE_BYTES 49152
#define GEMM_SMEM (2 * STAGE_BYTES)   // 98304 -> 2 CTAs/SM (192KB of 228KB)

__device__ __forceinline__ void gemm_load_chunk(
    char* smem, int stage, int c, int m0, int n0, int tid,
    const __nv_bfloat16* __restrict__ Ahi, const __nv_bfloat16* __restrict__ Alo,
    const __nv_bfloat16* __restrict__ Bhi, const __nv_bfloat16* __restrict__ Blo)
{
    const uint32_t sb = smem_to_u32(smem) + stage * STAGE_BYTES;
#pragma unroll
    for (int i = 0; i < 4; i++) {
        int u = tid + i * 256;          // 0..1023 16B units (A: 128 rows x 128B)
        int row = u >> 3, col = u & 7;
        uint32_t off = SWZ((uint32_t)(row * 128 + col * 16));
        size_t ga = (size_t)(m0 + row) * DD + c * 64 + col * 8;
        CP16(sb + SA_HI + off, Ahi + ga);
        CP16(sb + SA_LO + off, Alo + ga);
    }
#pragma unroll
    for (int i = 0; i < 2; i++) {
        int u = tid + i * 256;          // 0..511 (B: 64 rows x 128B)
        int row = u >> 3, col = u & 7;
        uint32_t off = SWZ((uint32_t)(row * 128 + col * 16));
        size_t gb = (size_t)(n0 + row) * DD + c * 64 + col * 8;
        CP16(sb + SB_HI + off, Bhi + gb);
        CP16(sb + SB_LO + off, Blo + gb);
    }
    CP_COMMIT();
}

__device__ __forceinline__ void gemm_mainloop(
    char* smem, int m0, int n0, int tid, int wm, int wn, int lane,
    const __nv_bfloat16* Ahi, const __nv_bfloat16* Alo,
    const __nv_bfloat16* Bhi, const __nv_bfloat16* Blo,
    float acc[4][2][4])
{
    gemm_load_chunk(smem, 0, 0, m0, n0, tid, Ahi, Alo, Bhi, Blo);
    const uint32_t sbase = smem_to_u32(smem);

    for (int c = 0; c < 8; c++) {
        CP_WAIT0();
        __syncthreads();
        if (c < 7)
            gemm_load_chunk(smem, (c + 1) & 1, c + 1, m0, n0, tid, Ahi, Alo, Bhi, Blo);
        const uint32_t st = sbase + (c & 1) * STAGE_BYTES;
#pragma unroll
        for (int kk = 0; kk < 4; kk++) {
            uint32_t ah[4][4], al[4][4], bh[4], bl[4];
#pragma unroll
            for (int mi = 0; mi < 4; mi++) {
                int row = wm * 64 + mi * 16 + (lane & 15);
                uint32_t off = SWZ((uint32_t)(row * 128 + kk * 32 + (lane >> 4) * 16));
                ldsm4(st + SA_HI + off, ah[mi]);
                ldsm4(st + SA_LO + off, al[mi]);
            }
            {
                int n = wn * 16 + (lane & 7) + ((lane & 16) ? 8 : 0);
                uint32_t off = SWZ((uint32_t)(n * 128 + kk * 32 + ((lane >> 3) & 1) * 16));
                ldsm4(st + SB_HI + off, bh);
                ldsm4(st + SB_LO + off, bl);
            }
#pragma unroll
            for (int mi = 0; mi < 4; mi++)
#pragma unroll
                for (int nt = 0; nt < 2; nt++) {
                    const uint32_t* h2 = &bh[nt * 2];
                    const uint32_t* l2 = &bl[nt * 2];
                    mma16816(acc[mi][nt], ah[mi], h2);
                    mma16816(acc[mi][nt], ah[mi], l2);
                    mma16816(acc[mi][nt], al[mi], h2);
                }
        }
    }
}

// ---------------- fused QKV GEMM: epilogue emits bf16 hi/lo (+ f32 v for dwc) ----------------
__global__ __launch_bounds__(256, 2)
void gemm_qkv(const __nv_bfloat16* __restrict__ Ahi, const __nv_bfloat16* __restrict__ Alo,
              const __nv_bfloat16* __restrict__ Bhi, const __nv_bfloat16* __restrict__ Blo,
              const float* __restrict__ pos)
{
    extern __shared__ char smem[];
    const int tid = threadIdx.x;
    const int wid = tid >> 5, lane = tid & 31;
    const int wm = wid & 1, wn = wid >> 1;     // 2m x 4n, warp tile 64x16
    const int m0 = blockIdx.y * 128;
    const int n0 = blockIdx.x * 64;            // 0..1472
    const int mode = blockIdx.x >> 3;          // 0=q 1=k 2=v
    const int ncol0 = n0 - mode * 512;

    float acc[4][2][4] = {};
    gemm_mainloop(smem, m0, n0, tid, wm, wn, lane, Ahi, Alo, Bhi, Blo, acc);

    __nv_bfloat16 *Ohi, *Olo;
    if (mode == 0)      { Ohi = g_qhi; Olo = g_qlo; }
    else if (mode == 1) { Ohi = g_khi; Olo = g_klo; }
    else                { Ohi = g_vhi; Olo = g_vlo; }

#pragma unroll
    for (int mi = 0; mi < 4; mi++) {
#pragma unroll
        for (int nt = 0; nt < 2; nt++) {
            int r0 = m0 + wm * 64 + mi * 16 + (lane >> 2);
            int col = ncol0 + wn * 16 + nt * 8 + (lane & 3) * 2;
#pragma unroll
            for (int half = 0; half < 2; half++) {
                int r = r0 + half * 8;
                float v0 = acc[mi][nt][half * 2 + 0];
                float v1 = acc[mi][nt][half * 2 + 1];
                if (mode == 1) {
                    const float2 pe = *(const float2*)(pos + (size_t)(r % NN) * DD + col);
                    v0 += pe.x; v1 += pe.y;
                }
                if (mode != 2) { v0 = fmaxf(v0, 0.f); v1 = fmaxf(v1, 0.f); }
                split_store(Ohi, Olo, (size_t)r * DD + col, v0, v1);
                if (mode == 2)
                    *(float2*)(g_v + (size_t)r * DD + col) = make_float2(v0, v1);
            }
        }
    }
}

// ---------------- final GEMM: out = y @ Wp + bp ----------------
__global__ __launch_bounds__(256, 2)
void gemm_out(const __nv_bfloat16* __restrict__ Ahi, const __nv_bfloat16* __restrict__ Alo,
              const __nv_bfloat16* __restrict__ Bhi, const __nv_bfloat16* __restrict__ Blo,
              float* __restrict__ C, const float* __restrict__ bias)
{
    extern __shared__ char smem[];
    const int tid = threadIdx.x;
    const int wid = tid >> 5, lane = tid & 31;
    const int wm = wid & 1, wn = wid >> 1;
    const int m0 = blockIdx.y * 128;
    const int n0 = blockIdx.x * 64;

    float acc[4][2][4] = {};
    gemm_mainloop(smem, m0, n0, tid, wm, wn, lane, Ahi, Alo, Bhi, Blo, acc);

#pragma unroll
    for (int mi = 0; mi < 4; mi++) {
#pragma unroll
        for (int nt = 0; nt < 2; nt++) {
            int r0 = m0 + wm * 64 + mi * 16 + (lane >> 2);
            int col = n0 + wn * 16 + nt * 8 + (lane & 3) * 2;
            const float2 bb = *(const float2*)(bias + col);
#pragma unroll
            for (int half = 0; half < 2; half++) {
                int r = r0 + half * 8;
                *(float2*)(C + (size_t)r * DD + col) =
                    make_float2(acc[mi][nt][half * 2 + 0] + bb.x,
                                acc[mi][nt][half * 2 + 1] + bb.y);
            }
        }
    }
}

// ---------------- ctx via HMMA + ldsm.trans, pre-split bf16 inputs (validated) ----------------
#define CTX_SMEM (3 * 16384)   // 49152

__global__ __launch_bounds__(128)
void ctx_mma_kernel()
{
    extern __shared__ char cs[];
    const int bh = blockIdx.x;          // 0..127
    const int s  = blockIdx.y;          // 0..SPLIT-1
    const int b = bh >> 3, h = bh & 7;
    const int tid = threadIdx.x, lane = tid & 31, wid = tid >> 5;
    const int wm = wid & 1, wn = wid >> 1;
    const uint32_t sb = smem_to_u32(cs);

    const size_t rowbase = ((size_t)(b * NN) + (size_t)s * TOKS) * DD + h * HDim;
    const __nv_bfloat16* src0 = g_khi + rowbase;
    const __nv_bfloat16* src1 = g_klo + rowbase;
    const __nv_bfloat16* src2 = g_vhi + rowbase;
    const __nv_bfloat16* src3 = g_vlo + rowbase;

    float acc[2][4][4] = {};
    float ks[2][2] = {};

#define CTX_LOAD(c, st) do {                                                    \
    uint32_t base_ = sb + (st) * 16384;                                         \
    _Pragma("unroll")                                                           \
    for (int i_ = 0; i_ < 8; i_++) {                                            \
        int u_ = tid + i_ * 128;                                                \
        int arr_ = u_ >> 8, rem_ = u_ & 255, row_ = rem_ >> 3, col_ = rem_ & 7; \
        uint32_t dst_ = base_ + arr_ * 4096 + SWZ((uint32_t)(row_ * 128 + col_ * 16)); \
        const __nv_bfloat16* sp_ = (arr_ == 0) ? src0 : (arr_ == 1) ? src1      \
                                  : (arr_ == 2) ? src2 : src3;                  \
        CP16(dst_, sp_ + (size_t)((c) * 32 + row_) * DD + col_ * 8);            \
    }                                                                           \
    CP_COMMIT();                                                                \
} while (0)

    CTX_LOAD(0, 0);
    CTX_LOAD(1, 1);

    for (int c = 0; c < 7; c++) {
        if (c < 6) { CP_WAIT1(); } else { CP_WAIT0(); }
        __syncthreads();
        if (c < 5) CTX_LOAD(c + 2, (c + 2) % 3);
        const uint32_t st = sb + (c % 3) * 16384;
#pragma unroll
        for (int kk = 0; kk < 2; kk++) {
            uint32_t ah[2][4], al[2][4], bh2[2][4], bl2[2][4];
#pragma unroll
            for (int mi = 0; mi < 2; mi++) {
                int wd = wm * 32 + mi * 16;
                int tokrow = kk * 16 + (lane & 7) + ((lane & 16) ? 8 : 0);
                uint32_t off = SWZ((uint32_t)(tokrow * 128 + wd * 2 + ((lane >> 3) & 1) * 16));
                ldsm4t(st + 0 + off, ah[mi]);
                ldsm4t(st + 4096 + off, al[mi]);
            }
#pragma unroll
            for (int g = 0; g < 2; g++) {
                int eb = wn * 32 + g * 16;
                int tokrow = kk * 16 + (lane & 7) + ((lane & 8) ? 8 : 0);
                uint32_t off = SWZ((uint32_t)(tokrow * 128 + eb * 2 + ((lane >> 4) & 1) * 16));
                ldsm4t(st + 8192 + off, bh2[g]);
                ldsm4t(st + 12288 + off, bl2[g]);
            }
#pragma unroll
            for (int mi = 0; mi < 2; mi++)
#pragma unroll
                for (int nt = 0; nt < 4; nt++) {
                    const uint32_t* h2 = &bh2[nt >> 1][(nt & 1) * 2];
                    const uint32_t* l2 = &bl2[nt >> 1][(nt & 1) * 2];
                    mma16816(acc[mi][nt], ah[mi], h2);
                    mma16816(acc[mi][nt], ah[mi], l2);
                    mma16816(acc[mi][nt], al[mi], h2);
                }
            if (wn == 0) {
#pragma unroll
                for (int mi = 0; mi < 2; mi++)
#pragma unroll
                    for (int rr = 0; rr < 2; rr++) {
                        float2 x0 = __bfloat1622float2(*(__nv_bfloat162*)&ah[mi][rr]);
                        float2 x2 = __bfloat1622float2(*(__nv_bfloat162*)&ah[mi][rr + 2]);
                        float2 y0 = __bfloat1622float2(*(__nv_bfloat162*)&al[mi][rr]);
                        float2 y2 = __bfloat1622float2(*(__nv_bfloat162*)&al[mi][rr + 2]);
                        ks[mi][rr] += x0.x + x0.y + x2.x + x2.y + y0.x + y0.y + y2.x + y2.y;
                    }
            }
        }
    }

    float* cp = g_ctx_part + ((size_t)s * 128 + bh) * 4096;
#pragma unroll
    for (int mi = 0; mi < 2; mi++)
#pragma unroll
        for (int nt = 0; nt < 4; nt++) {
            int r = wm * 32 + mi * 16 + (lane >> 2);
            int col = wn * 32 + nt * 8 + (lane & 3) * 2;
            *(float2*)&cp[r * 64 + col] = make_float2(acc[mi][nt][0], acc[mi][nt][1]);
            *(float2*)&cp[(r + 8) * 64 + col] = make_float2(acc[mi][nt][2], acc[mi][nt][3]);
        }

#pragma unroll
    for (int mi = 0; mi < 2; mi++)
#pragma unroll
        for (int rr = 0; rr < 2; rr++) {
            ks[mi][rr] += __shfl_xor_sync(0xffffffffu, ks[mi][rr], 1);
            ks[mi][rr] += __shfl_xor_sync(0xffffffffu, ks[mi][rr], 2);
        }
    if (wn == 0 && (lane & 3) == 0) {
        float* kp = g_ksum_part + ((size_t)s * 128 + bh) * 64;
#pragma unroll
        for (int mi = 0; mi < 2; mi++)
#pragma unroll
            for (int rr = 0; rr < 2; rr++)
                kp[wm * 32 + mi * 16 + (lane >> 2) + rr * 8] = ks[mi][rr];
    }
}

// ---------------- reduce: sum partials, emit ctx bf16 hi/lo + ksum f32 ----------------
__global__ void reduce_kernel()
{
    const int idx = blockIdx.x * 256 + threadIdx.x;
    if (idx < 128 * 4096) {
        float s = 0.f;
#pragma unroll
        for (int p = 0; p < SPLIT; p++) s += g_ctx_part[(size_t)p * 128 * 4096 + idx];
        __nv_bfloat16 hi = __float2bfloat16(s);
        g_ctxhi[idx] = hi;
        g_ctxlo[idx] = __float2bfloat16(s - __bfloat162float(hi));
    } else {
        const int i2 = idx - 128 * 4096;
        if (i2 < 128 * 64) {
            float s = 0.f;
#pragma unroll
            for (int p = 0; p < SPLIT; p++) s += g_ksum_part[(size_t)p * 128 * 64 + i2];
            g_ksum[i2] = s;
        }
    }
}

// ---------------- attn via HMMA: y = (q @ ctx) * dinv ----------------
__global__ __launch_bounds__(128)
void attn_mma_kernel()
{
    __shared__ __align__(16) char abuf[4][8192];   // qhi, qlo, ctxhi, ctxlo
    __shared__ float ksumS[64];
    __shared__ float dinv[64];

    const int n0 = blockIdx.x * 64;
    const int bh = blockIdx.y;
    const int b = bh >> 3, h = bh & 7;
    const int tid = threadIdx.x, lane = tid & 31, wn = tid >> 5;
    const uint32_t sb = smem_to_u32(abuf);

    const size_t qbase = ((size_t)(b * NN) + n0) * DD + h * HDim;
#pragma unroll
    for (int i = 0; i < 16; i++) {
        int u = tid + i * 128;
        int arr = u >> 9, rem = u & 511, row = rem >> 3, col = rem & 7;
        uint32_t dst = sb + arr * 8192 + SWZ((uint32_t)(row * 128 + col * 16));
        const __nv_bfloat16* src;
        if (arr == 0)      src = g_qhi + qbase + (size_t)row * DD + col * 8;
        else if (arr == 1) src = g_qlo + qbase + (size_t)row * DD + col * 8;
        else if (arr == 2) src = g_ctxhi + (size_t)bh * 4096 + row * 64 + col * 8;
        else               src = g_ctxlo + (size_t)bh * 4096 + row * 64 + col * 8;
        CP16(dst, src);
    }
    CP_COMMIT();
    if (tid >= 64) ksumS[tid - 64] = g_ksum[bh * 64 + tid - 64];
    CP_WAIT0();
    __syncthreads();

    if (tid < 64) {
        float ssum = 0.f;
#pragma unroll
        for (int c8 = 0; c8 < 8; c8++) {
            uint32_t off = SWZ((uint32_t)(tid * 128 + c8 * 16));
#pragma unroll
            for (int j = 0; j < 8; j++) {
                float qv = __bfloat162float(*(__nv_bfloat16*)(abuf[0] + off + j * 2))
                         + __bfloat162float(*(__nv_bfloat16*)(abuf[1] + off + j * 2));
                ssum = fmaf(qv, ksumS[c8 * 8 + j], ssum);
            }
        }
        dinv[tid] = 1.0f / (ssum + 1e-6f);
    }
    __syncthreads();

    float acc[4][2][4] = {};
    const uint32_t q_hi = sb, q_lo = sb + 8192, c_hi = sb + 16384, c_lo = sb + 24576;
#pragma unroll
    for (int kk = 0; kk < 4; kk++) {
        uint32_t ah[4][4], al[4][4], bh2[4], bl2[4];
#pragma unroll
        for (int mi = 0; mi < 4; mi++) {
            int row = mi * 16 + (lane & 15);
            uint32_t off = SWZ((uint32_t)(row * 128 + kk * 32 + (lane >> 4) * 16));
            ldsm4(q_hi + off, ah[mi]);
            ldsm4(q_lo + off, al[mi]);
        }
        {
            int drow = kk * 16 + (lane & 7) + ((lane & 8) ? 8 : 0);
            uint32_t off = SWZ((uint32_t)(drow * 128 + wn * 32 + ((lane >> 4) & 1) * 16));
            ldsm4t(c_hi + off, bh2);
            ldsm4t(c_lo + off, bl2);
        }
#pragma unroll
        for (int mi = 0; mi < 4; mi++)
#pragma unroll
            for (int nt = 0; nt < 2; nt++) {
                mma16816(acc[mi][nt], ah[mi], &bh2[nt * 2]);
                mma16816(acc[mi][nt], ah[mi], &bl2[nt * 2]);
                mma16816(acc[mi][nt], al[mi], &bh2[nt * 2]);
            }
    }

    float* yb = g_y + ((size_t)bh * NN + n0) * HDim;
#pragma unroll
    for (int mi = 0; mi < 4; mi++)
#pragma unroll
        for (int nt = 0; nt < 2; nt++) {
            int r = mi * 16 + (lane >> 2);
            int col = wn * 16 + nt * 8 + (lane & 3) * 2;
            float d0 = dinv[r], d1 = dinv[r + 8];
            *(float2*)&yb[(size_t)r * 64 + col] =
                make_float2(acc[mi][nt][0] * d0, acc[mi][nt][1] * d0);
            *(float2*)&yb[(size_t)(r + 8) * 64 + col] =
                make_float2(acc[mi][nt][2] * d1, acc[mi][nt][3] * d1);
        }
}

// ---------------- dwc: depthwise 5x5 over f32 v + fused bf16 split of y ----------------
__global__ __launch_bounds__(256)
void dwc_kernel(const float* __restrict__ w, const float* __restrict__ bias)
{
    const int bh = blockIdx.y;
    const int b = bh >> 3, h = bh & 7;
    const int tid = threadIdx.x;

    __shared__ float ws[64 * 25];
    __shared__ float bs[64];
    for (int i = tid; i < 64 * 25; i += 256) ws[i] = w[i];
    if (tid < 64) bs[tid] = bias[tid];
    __syncthreads();

    const int c = tid & 63;
    const int p = blockIdx.x * 4 + (tid >> 6);
    const int pi = p / HH, pj = p % HH;

    const float* vbase = g_v + (size_t)(b * NN) * DD + h * HDim + c;
    float acc = 0.f;
#pragma unroll
    for (int di = 0; di < 5; di++) {
        const int ii = pi + di - 2;
        if ((unsigned)ii < (unsigned)HH) {
#pragma unroll
            for (int dj = 0; dj < 5; dj++) {
                const int jj = pj + dj - 2;
                if ((unsigned)jj < (unsigned)HH)
                    acc = fmaf(ws[c * 25 + di * 5 + dj],
                               vbase[(size_t)(ii * HH + jj) * DD], acc);
            }
        }
    }
    const size_t yi = ((size_t)bh * NN + p) * HDim + c;
    float total = g_y[yi] + acc + bs[c];
    __nv_bfloat16 hi = __float2bfloat16(total);
    g_yhi[yi] = hi;
    g_ylo[yi] = __float2bfloat16(total - __bfloat162float(hi));
}

// ---------------- launch ----------------
extern "C" void kernel_launch(void* const* d_in, const int* in_sizes, int n_in,
                              void* d_out, int out_size)
{
    const float* x    = (const float*)d_in[0];
    const float* Wq   = (const float*)d_in[1];
    const float* Wkv  = (const float*)d_in[2];
    const float* pos  = (const float*)d_in[3];
    const float* dwcw = (const float*)d_in[4];
    const float* dwcb = (const float*)d_in[5];
    const float* Wp   = (const float*)d_in[6];
    const float* bp   = (const float*)d_in[7];
    float* out = (float*)d_out;

    __nv_bfloat16 *xhip, *xlop, *yhip, *ylop, *whip, *wlop;
    cudaGetSymbolAddress((void**)&xhip, g_xhi);
    cudaGetSymbolAddress((void**)&xlop, g_xlo);
    cudaGetSymbolAddress((void**)&yhip, g_yhi);
    cudaGetSymbolAddress((void**)&ylop, g_ylo);
    cudaGetSymbolAddress((void**)&whip, g_whi);
    cudaGetSymbolAddress((void**)&wlop, g_wlo);

    cudaFuncSetAttribute(gemm_qkv, cudaFuncAttributeMaxDynamicSharedMemorySize, GEMM_SMEM);
    cudaFuncSetAttribute(gemm_out, cudaFuncAttributeMaxDynamicSharedMemorySize, GEMM_SMEM);
    cudaFuncSetAttribute(ctx_mma_kernel, cudaFuncAttributeMaxDynamicSharedMemorySize, CTX_SMEM);

    split_x_kernel<<<(MM * DD / 4) / 256, 256>>>(x);
    prep_w_kernel<<<(DD * DD) / 256, 256>>>(Wq, Wkv, Wp);

    const size_t WSZ = (size_t)DD * DD;
    gemm_qkv<<<dim3(24, MM / 128), 256, GEMM_SMEM>>>(xhip, xlop, whip, wlop, pos);

    ctx_mma_kernel<<<dim3(128, SPLIT), 128, CTX_SMEM>>>();
    reduce_kernel<<<(128 * 4096 + 128 * 64) / 256, 256>>>();
    attn_mma_kernel<<<dim3(NN / 64, 128), 128>>>();
    dwc_kernel<<<dim3(NN / 4, 128), 256>>>(dwcw, dwcb);

    gemm_out<<<dim3(8, MM / 128), 256, GEMM_SMEM>>>(
        yhip, ylop, whip + 3 * WSZ, wlop + 3 * WSZ, out, bp);
}